// round 5
// baseline (speedup 1.0000x reference)
#include <cuda_runtime.h>

#define NN      64
#define RC      8.0f
#define PI_F    3.14159265358979323846f
#define MAX_ATOMS 32768

// packed[i] = (pos.x, pos.y, pos.z, bitcast(type)); slot [n] = dummy (type=-1)
__device__ float4 g_packed[MAX_ATOMS + 1];

static __device__ __forceinline__ float fsqrt_approx(float x) {
    float y; asm("sqrt.approx.f32 %0, %1;" : "=f"(y) : "f"(x)); return y;
}
static __device__ __forceinline__ float fcos_approx(float x) {
    float y; asm("cos.approx.f32 %0, %1;" : "=f"(y) : "f"(x)); return y;
}
static __device__ __forceinline__ unsigned long long pack2(float lo, float hi) {
    unsigned long long r;
    asm("mov.b64 %0, {%1, %2};" : "=l"(r) : "f"(lo), "f"(hi));
    return r;
}
static __device__ __forceinline__ void fma2(unsigned long long& d,
                                            unsigned long long a,
                                            unsigned long long b) {
    asm("fma.rn.f32x2 %0, %1, %2, %0;" : "+l"(d) : "l"(a), "l"(b));
}
static __device__ __forceinline__ void unpack2(unsigned long long v, float& lo, float& hi) {
    asm("mov.b64 {%0, %1}, %2;" : "=f"(lo), "=f"(hi) : "l"(v));
}

__global__ void pack_kernel(const int* __restrict__ types,
                            const float* __restrict__ pos, int n)
{
    int i = blockIdx.x * blockDim.x + threadIdx.x;
    if (i < n) {
        float4 p;
        p.x = pos[i * 3 + 0];
        p.y = pos[i * 3 + 1];
        p.z = pos[i * 3 + 2];
        p.w = __int_as_float(types[i]);
        g_packed[i] = p;
    }
    if (i == n)
        g_packed[n] = make_float4(0.0f, 0.0f, 0.0f, __int_as_float(-1));
}

// 8 lanes per atom, 4 atoms per warp, 4 warps/block -> 16 atoms/block, grid=1250.
// Lane s owns edges [s*8, s*8+8); ALL 8 pos+type gathers issued up-front for
// max MLP. Packed f32x2 Chebyshev accumulators, R2-style 8-lane butterfly.
__global__ __launch_bounds__(128) void radial_desc_kernel(
    const int*   __restrict__ nbr,
    const float* __restrict__ offs,
    const float* __restrict__ ctab,
    float*       __restrict__ out,
    int n_atoms)
{
    __shared__ float c_sh[1024];   // 4 KB, direct copy
    for (int i = threadIdx.x; i < 1024; i += 128)
        c_sh[i] = ctab[i];
    __syncthreads();

    const int lane = threadIdx.x & 31;
    const int warp = threadIdx.x >> 5;
    const int s    = lane & 7;    // lane within 8-lane group
    const int g    = lane >> 3;   // atom slot within warp

    const int atom = blockIdx.x * 16 + warp * 4 + g;
    const bool ok  = (atom < n_atoms);
    const int a    = ok ? atom : 0;

    const float4 pa = g_packed[a];
    const int    ti = __float_as_int(pa.w);

    // ---- issue ALL loads / gathers up-front ----
    const int4*   nb4 = reinterpret_cast<const int4*>(nbr)    + (long)a * 16 + s * 2;
    const float4* ob4 = reinterpret_cast<const float4*>(offs) + (long)a * 48 + s * 6;

    const int4 nvA = __ldcs(nb4 + 0);
    const int4 nvB = __ldcs(nb4 + 1);

    int ia[8];
    ia[0] = (nvA.x < 0) ? n_atoms : nvA.x;
    ia[1] = (nvA.y < 0) ? n_atoms : nvA.y;
    ia[2] = (nvA.z < 0) ? n_atoms : nvA.z;
    ia[3] = (nvA.w < 0) ? n_atoms : nvA.w;
    ia[4] = (nvB.x < 0) ? n_atoms : nvB.x;
    ia[5] = (nvB.y < 0) ? n_atoms : nvB.y;
    ia[6] = (nvB.z < 0) ? n_atoms : nvB.z;
    ia[7] = (nvB.w < 0) ? n_atoms : nvB.w;

    float4 P[8];
    #pragma unroll
    for (int e = 0; e < 8; e++)
        P[e] = g_packed[ia[e]];        // 8 independent LDG.128 gathers in flight

    const float4 oA0 = __ldcs(ob4 + 0);
    const float4 oA1 = __ldcs(ob4 + 1);
    const float4 oA2 = __ldcs(ob4 + 2);
    const float4 oB0 = __ldcs(ob4 + 3);
    const float4 oB1 = __ldcs(ob4 + 4);
    const float4 oB2 = __ldcs(ob4 + 5);

    const float eox[8] = { oA0.x, oA0.w, oA1.z, oA2.y,  oB0.x, oB0.w, oB1.z, oB2.y };
    const float eoy[8] = { oA0.y, oA1.x, oA1.w, oA2.z,  oB0.y, oB1.x, oB1.w, oB2.z };
    const float eoz[8] = { oA0.z, oA1.y, oA2.x, oA2.w,  oB0.z, oB1.y, oB2.x, oB2.w };

    unsigned long long Gp[16];         // Gp[t*4+i] = {G[t][2i], G[t][2i+1]}
    #pragma unroll
    for (int i = 0; i < 16; i++) Gp[i] = 0ull;

    #pragma unroll
    for (int e = 0; e < 8; e++) {
        const float dx = P[e].x + eox[e] - pa.x;
        const float dy = P[e].y + eoy[e] - pa.y;
        const float dz = P[e].z + eoz[e] - pa.z;
        const int   tj = __float_as_int(P[e].w);

        const float r2 = dx * dx + dy * dy + dz * dz;
        const float r  = fsqrt_approx(r2);

        float h = 0.25f * fcos_approx(r * (PI_F / RC)) + 0.25f;
        h = (r < RC) ? h : 0.0f;

        const float u  = r * (1.0f / RC) - 1.0f;
        const float x  = 2.0f * u * u - 1.0f;
        const float tw = x + x;
        const float T2 = tw * x  - 1.0f;
        const float T3 = tw * T2 - x;
        const float T4 = tw * T3 - T2;
        const float T5 = tw * T4 - T3;
        const float T6 = tw * T5 - T4;
        const float T7 = tw * T6 - T5;

        const unsigned long long V0 = pack2(1.0f, x);   // T0, T1
        const unsigned long long V1 = pack2(T2, T3);
        const unsigned long long V2 = pack2(T4, T5);
        const unsigned long long V3 = pack2(T6, T7);
        const unsigned long long H  = pack2(h, h);

        #pragma unroll
        for (int t = 0; t < 4; t++) {
            const unsigned long long W = (tj == t) ? H : 0ull;
            fma2(Gp[t * 4 + 0], W, V0);
            fma2(Gp[t * 4 + 1], W, V1);
            fma2(Gp[t * 4 + 2], W, V2);
            fma2(Gp[t * 4 + 3], W, V3);
        }
    }

    // unpack to v[32], v[t*8+k]
    float v[32];
    #pragma unroll
    for (int i = 0; i < 16; i++) unpack2(Gp[i], v[i * 2], v[i * 2 + 1]);

    // ---- halving-butterfly reduction of 32 values over the 8-lane group ----
    const bool hi4 = (s & 4) != 0;
    const bool hi2 = (s & 2) != 0;
    const bool hi1 = (s & 1) != 0;

    float v1[16];
    #pragma unroll
    for (int i = 0; i < 16; i++) {
        const float send = hi4 ? v[i] : v[i + 16];
        const float recv = __shfl_xor_sync(0xffffffffu, send, 4);
        v1[i] = (hi4 ? v[i + 16] : v[i]) + recv;
    }
    float v2[8];
    #pragma unroll
    for (int i = 0; i < 8; i++) {
        const float send = hi2 ? v1[i] : v1[i + 8];
        const float recv = __shfl_xor_sync(0xffffffffu, send, 2);
        v2[i] = (hi2 ? v1[i + 8] : v1[i]) + recv;
    }
    float v3[4];
    #pragma unroll
    for (int i = 0; i < 4; i++) {
        const float send = hi1 ? v2[i] : v2[i + 4];
        const float recv = __shfl_xor_sync(0xffffffffu, send, 1);
        v3[i] = (hi1 ? v2[i + 4] : v2[i]) + recv;
    }
    // lane s holds totals for t = ((s&4)>>1)|((s&2)>>1), k = (s&1)*4 + k'
    const int tl = ((s & 4) >> 1) | ((s & 2) >> 1);

    // F[t][k] = G[t][k] + G[t][0]  (folds the (T_k + 1) term; k=0 -> 2*G[t][0])
    const float g0 = __shfl_sync(0xffffffffu, v3[0], lane & ~1);
    const float F0 = v3[0] + g0;
    const float F1 = v3[1] + g0;
    const float F2 = v3[2] + g0;
    const float F3 = v3[3] + g0;

    const float4* c4p = reinterpret_cast<const float4*>(c_sh);
    const int base = ((ti * 4 + tl) * 8) * 2 + (s & 1);
    float p[8];
    #pragma unroll
    for (int d = 0; d < 8; d++) {
        const float4 c = c4p[base + d * 2];
        p[d] = c.x * F0 + c.y * F1 + c.z * F2 + c.w * F3;
    }

    float q[4];
    #pragma unroll
    for (int i = 0; i < 4; i++) {
        const float send = hi4 ? p[i] : p[i + 4];
        const float recv = __shfl_xor_sync(0xffffffffu, send, 4);
        q[i] = (hi4 ? p[i + 4] : p[i]) + recv;
    }
    float rr[2];
    #pragma unroll
    for (int i = 0; i < 2; i++) {
        const float send = hi2 ? q[i] : q[i + 2];
        const float recv = __shfl_xor_sync(0xffffffffu, send, 2);
        rr[i] = (hi2 ? q[i + 2] : q[i]) + recv;
    }
    {
        const float send = hi1 ? rr[0] : rr[1];
        const float recv = __shfl_xor_sync(0xffffffffu, send, 1);
        const float o = (hi1 ? rr[1] : rr[0]) + recv;
        if (ok) out[(long)atom * 8 + s] = o;   // 128B contiguous per warp
    }
}

extern "C" void kernel_launch(void* const* d_in, const int* in_sizes, int n_in,
                              void* d_out, int out_size) {
    const int*   types = (const int*)  d_in[0];
    const float* pos   = (const float*)d_in[1];
    const int*   nbr   = (const int*)  d_in[2];
    const float* offs  = (const float*)d_in[3];
    const float* ctab  = (const float*)d_in[4];
    float* out = (float*)d_out;

    int n_atoms = in_sizes[0];
    if (n_atoms > MAX_ATOMS) n_atoms = MAX_ATOMS;

    pack_kernel<<<(n_atoms + 1 + 255) / 256, 256>>>(types, pos, n_atoms);

    const int atoms_per_block = 16;               // 4 warps * 4 atoms
    const int grid = (n_atoms + atoms_per_block - 1) / atoms_per_block;
    radial_desc_kernel<<<grid, 128>>>(nbr, offs, ctab, out, n_atoms);
}

// round 6
// speedup vs baseline: 1.0017x; 1.0017x over previous
#include <cuda_runtime.h>

#define RC        8.0f
#define PI_F      3.14159265358979323846f
#define MAX_ATOMS 27000
#define FPSCALE   32768.0f
#define INV_FPSCALE (1.0f / 32768.0f)

// fixed-point packed atoms: x:21b (+/-32), y:21b (+/-32), z:20b (+/-16), type:2b
// w.x = x[20:0] | y[10:0]<<21 ;  w.y = y[20:11] | z[19:0]<<10 | t<<30
__device__ uint2 g_q[MAX_ATOMS + 1];

static __device__ __forceinline__ float fsqrt_approx(float x) {
    float y; asm("sqrt.approx.f32 %0, %1;" : "=f"(y) : "f"(x)); return y;
}
static __device__ __forceinline__ float fcos_approx(float x) {
    float y; asm("cos.approx.f32 %0, %1;" : "=f"(y) : "f"(x)); return y;
}

__global__ void pack_kernel(const int* __restrict__ types,
                            const float* __restrict__ pos, int n)
{
    int i = blockIdx.x * blockDim.x + threadIdx.x;
    if (i < n) {
        const int xq = __float2int_rn(pos[i * 3 + 0] * FPSCALE);
        const int yq = __float2int_rn(pos[i * 3 + 1] * FPSCALE);
        const int zq = __float2int_rn(pos[i * 3 + 2] * FPSCALE);
        const unsigned t = (unsigned)types[i];
        uint2 w;
        w.x = ((unsigned)xq & 0x1FFFFFu) | ((unsigned)yq << 21);
        w.y = (((unsigned)yq >> 11) & 0x3FFu)
            | (((unsigned)zq & 0xFFFFFu) << 10)
            | (t << 30);
        g_q[i] = w;
    }
    if (i == n) {
        // dummy: x = +31 units -> r > RC for any real atom -> h = 0
        uint2 w;
        w.x = (unsigned)(31 * 32768) & 0x1FFFFFu;
        w.y = 0u;
        g_q[n] = w;
    }
}

static __device__ __forceinline__ void unpack_q(uint2 w, int& x, int& y, int& z, int& t) {
    x = ((int)(w.x << 11)) >> 11;
    const unsigned y21 = (w.x >> 21) | ((w.y & 0x3FFu) << 11);
    y = ((int)(y21 << 11)) >> 11;
    z = ((int)(w.y << 2)) >> 12;
    t = (int)(w.y >> 30);
}

// One CTA per SM (single wave). Whole packed atom table lives in dynamic smem;
// the per-edge random gather is an LDS.64 instead of an L1tex 32-line LDG.
// 8 lanes per atom, 4 atoms per warp, 16 warps -> 64 atoms per loop iteration.
__global__ __launch_bounds__(512, 1) void radial_desc_kernel(
    const int*   __restrict__ nbr,
    const float* __restrict__ offs,
    const float* __restrict__ ctab,
    float*       __restrict__ out,
    int n_atoms, int n_cta)
{
    extern __shared__ char smem[];
    uint2* tab = reinterpret_cast<uint2*>(smem);
    const int n1 = n_atoms + 1;
    float* c_sh = reinterpret_cast<float*>(smem + (((size_t)n1 * 8 + 15) & ~(size_t)15));

    // cooperative table + coeff load
    for (int i = threadIdx.x; i < n1; i += 512) tab[i] = g_q[i];
    for (int i = threadIdx.x; i < 1024; i += 512) c_sh[i] = ctab[i];
    __syncthreads();

    const int c     = blockIdx.x;
    const int start = (int)(((long long)c * n_atoms) / n_cta);
    const int end   = (int)(((long long)(c + 1) * n_atoms) / n_cta);
    const int count = end - start;

    const int lane = threadIdx.x & 31;
    const int warp = threadIdx.x >> 5;
    const int s    = lane & 7;    // lane within 8-lane group
    const int g    = lane >> 3;   // atom slot within warp

    const bool hi4 = (s & 4) != 0;
    const bool hi2 = (s & 2) != 0;
    const bool hi1 = (s & 1) != 0;

    for (int base = warp * 4; base < count; base += 64) {
        const int gi   = base + g;
        const bool ok  = gi < count;
        const int atom = start + (ok ? gi : (count - 1));

        // own atom (from smem table)
        int xa, ya, za, ti;
        unpack_q(tab[atom], xa, ya, za, ti);

        // ---- streaming loads (evict-first; L1 is mostly smem carveout now) ----
        const int4*   nb4 = reinterpret_cast<const int4*>(nbr)    + (long)atom * 16 + s * 2;
        const float4* ob4 = reinterpret_cast<const float4*>(offs) + (long)atom * 48 + s * 6;

        const int4 nvA = __ldcs(nb4 + 0);
        const int4 nvB = __ldcs(nb4 + 1);

        int ia[8];
        ia[0] = (nvA.x < 0) ? n_atoms : nvA.x;
        ia[1] = (nvA.y < 0) ? n_atoms : nvA.y;
        ia[2] = (nvA.z < 0) ? n_atoms : nvA.z;
        ia[3] = (nvA.w < 0) ? n_atoms : nvA.w;
        ia[4] = (nvB.x < 0) ? n_atoms : nvB.x;
        ia[5] = (nvB.y < 0) ? n_atoms : nvB.y;
        ia[6] = (nvB.z < 0) ? n_atoms : nvB.z;
        ia[7] = (nvB.w < 0) ? n_atoms : nvB.w;

        uint2 W[8];
        #pragma unroll
        for (int e = 0; e < 8; e++) W[e] = tab[ia[e]];     // 8 x LDS.64 gathers

        const float4 oA0 = __ldcs(ob4 + 0);
        const float4 oA1 = __ldcs(ob4 + 1);
        const float4 oA2 = __ldcs(ob4 + 2);
        const float4 oB0 = __ldcs(ob4 + 3);
        const float4 oB1 = __ldcs(ob4 + 4);
        const float4 oB2 = __ldcs(ob4 + 5);

        const float eox[8] = { oA0.x, oA0.w, oA1.z, oA2.y,  oB0.x, oB0.w, oB1.z, oB2.y };
        const float eoy[8] = { oA0.y, oA1.x, oA1.w, oA2.z,  oB0.y, oB1.x, oB1.w, oB2.z };
        const float eoz[8] = { oA0.z, oA1.y, oA2.x, oA2.w,  oB0.z, oB1.y, oB2.x, oB2.w };

        float G[4][8];
        #pragma unroll
        for (int t = 0; t < 4; t++)
            #pragma unroll
            for (int k = 0; k < 8; k++)
                G[t][k] = 0.0f;

        #pragma unroll
        for (int e = 0; e < 8; e++) {
            int xj, yj, zj, tj;
            unpack_q(W[e], xj, yj, zj, tj);

            // exact integer diffs, then scale folds into an FMA with the offset
            const float dx = fmaf((float)(xj - xa), INV_FPSCALE, eox[e]);
            const float dy = fmaf((float)(yj - ya), INV_FPSCALE, eoy[e]);
            const float dz = fmaf((float)(zj - za), INV_FPSCALE, eoz[e]);

            const float r2 = dx * dx + dy * dy + dz * dz;
            const float r  = fsqrt_approx(r2);

            float h = 0.25f * fcos_approx(r * (PI_F / RC)) + 0.25f;
            h = (r < RC) ? h : 0.0f;

            const float u  = r * (1.0f / RC) - 1.0f;
            const float x  = 2.0f * u * u - 1.0f;
            const float tw = x + x;

            float T[8];
            T[1] = x;
            T[2] = tw * x - 1.0f;
            #pragma unroll
            for (int k = 3; k < 8; k++) T[k] = tw * T[k - 1] - T[k - 2];

            #pragma unroll
            for (int t = 0; t < 4; t++) {
                const float wh = (tj == t) ? h : 0.0f;
                G[t][0] += wh;                        // T0 == 1
                #pragma unroll
                for (int k = 1; k < 8; k++) G[t][k] += wh * T[k];
            }
        }

        // ---- halving-butterfly reduction of 32 values over the 8-lane group ----
        float* v = &G[0][0];
        float v1[16];
        #pragma unroll
        for (int i = 0; i < 16; i++) {
            const float send = hi4 ? v[i] : v[i + 16];
            const float recv = __shfl_xor_sync(0xffffffffu, send, 4);
            v1[i] = (hi4 ? v[i + 16] : v[i]) + recv;
        }
        float v2[8];
        #pragma unroll
        for (int i = 0; i < 8; i++) {
            const float send = hi2 ? v1[i] : v1[i + 8];
            const float recv = __shfl_xor_sync(0xffffffffu, send, 2);
            v2[i] = (hi2 ? v1[i + 8] : v1[i]) + recv;
        }
        float v3[4];
        #pragma unroll
        for (int i = 0; i < 4; i++) {
            const float send = hi1 ? v2[i] : v2[i + 4];
            const float recv = __shfl_xor_sync(0xffffffffu, send, 1);
            v3[i] = (hi1 ? v2[i + 4] : v2[i]) + recv;
        }
        // lane s holds totals for t = ((s&4)>>1)|((s&2)>>1), k = (s&1)*4 + k'
        const int tl = ((s & 4) >> 1) | ((s & 2) >> 1);

        // F[t][k] = G[t][k] + G[t][0]  (folds the (T_k + 1) term)
        const float g0 = __shfl_sync(0xffffffffu, v3[0], lane & ~1);
        const float F0 = v3[0] + g0;
        const float F1 = v3[1] + g0;
        const float F2 = v3[2] + g0;
        const float F3 = v3[3] + g0;

        const float4* c4p = reinterpret_cast<const float4*>(c_sh);
        const int cbase = ((ti * 4 + tl) * 8) * 2 + (s & 1);
        float p[8];
        #pragma unroll
        for (int d = 0; d < 8; d++) {
            const float4 cc = c4p[cbase + d * 2];
            p[d] = cc.x * F0 + cc.y * F1 + cc.z * F2 + cc.w * F3;
        }

        float q[4];
        #pragma unroll
        for (int i = 0; i < 4; i++) {
            const float send = hi4 ? p[i] : p[i + 4];
            const float recv = __shfl_xor_sync(0xffffffffu, send, 4);
            q[i] = (hi4 ? p[i + 4] : p[i]) + recv;
        }
        float rr[2];
        #pragma unroll
        for (int i = 0; i < 2; i++) {
            const float send = hi2 ? q[i] : q[i + 2];
            const float recv = __shfl_xor_sync(0xffffffffu, send, 2);
            rr[i] = (hi2 ? q[i + 2] : q[i]) + recv;
        }
        {
            const float send = hi1 ? rr[0] : rr[1];
            const float recv = __shfl_xor_sync(0xffffffffu, send, 1);
            const float o = (hi1 ? rr[1] : rr[0]) + recv;
            if (ok) out[(long)atom * 8 + s] = o;
        }
    }
}

extern "C" void kernel_launch(void* const* d_in, const int* in_sizes, int n_in,
                              void* d_out, int out_size) {
    const int*   types = (const int*)  d_in[0];
    const float* pos   = (const float*)d_in[1];
    const int*   nbr   = (const int*)  d_in[2];
    const float* offs  = (const float*)d_in[3];
    const float* ctab  = (const float*)d_in[4];
    float* out = (float*)d_out;

    int n_atoms = in_sizes[0];
    if (n_atoms > MAX_ATOMS) n_atoms = MAX_ATOMS;

    pack_kernel<<<(n_atoms + 1 + 255) / 256, 256>>>(types, pos, n_atoms);

    int n_sm = 148;
    cudaDeviceGetAttribute(&n_sm, cudaDevAttrMultiProcessorCount, 0);

    const size_t tab_bytes = (((size_t)(n_atoms + 1) * 8 + 15) & ~(size_t)15);
    const size_t sh_bytes  = tab_bytes + 1024 * sizeof(float);

    static int configured_bytes = 0;
    if ((int)sh_bytes != configured_bytes) {
        cudaFuncSetAttribute(radial_desc_kernel,
                             cudaFuncAttributeMaxDynamicSharedMemorySize,
                             (int)sh_bytes);
        configured_bytes = (int)sh_bytes;
    }

    radial_desc_kernel<<<n_sm, 512, sh_bytes>>>(nbr, offs, ctab, out,
                                                n_atoms, n_sm);
}

// round 7
// speedup vs baseline: 1.0292x; 1.0274x over previous
#include <cuda_runtime.h>

#define NN      64
#define RC      8.0f
#define PI_F    3.14159265358979323846f
#define MAX_ATOMS 32768

// packed[i] = (pos.x, pos.y, pos.z, bitcast(type)); slot [n] = dummy (type=-1)
__device__ float4 g_packed[MAX_ATOMS + 1];

static __device__ __forceinline__ float fsqrt_approx(float x) {
    float y; asm("sqrt.approx.f32 %0, %1;" : "=f"(y) : "f"(x)); return y;
}
static __device__ __forceinline__ float fcos_approx(float x) {
    float y; asm("cos.approx.f32 %0, %1;" : "=f"(y) : "f"(x)); return y;
}

__global__ void pack_kernel(const int* __restrict__ types,
                            const float* __restrict__ pos, int n)
{
    int i = blockIdx.x * blockDim.x + threadIdx.x;
    if (i < n) {
        float4 p;
        p.x = pos[i * 3 + 0];
        p.y = pos[i * 3 + 1];
        p.z = pos[i * 3 + 2];
        p.w = __int_as_float(types[i]);
        g_packed[i] = p;
    }
    if (i == n)
        g_packed[n] = make_float4(0.0f, 0.0f, 0.0f, __int_as_float(-1));
}

// 8 lanes per atom, 4 atoms per warp, 8 warps/block -> 32 atoms/block, 625 blocks.
// __launch_bounds__(256,4): 64-reg cap -> 4 blocks/SM -> 32 warps/SM, 1.03 waves.
// Lane s owns edges [s*8, s*8+8) in two 4-edge batches (bounded live registers).
__global__ __launch_bounds__(256, 4) void radial_desc_kernel(
    const int*   __restrict__ nbr,
    const float* __restrict__ offs,
    const float* __restrict__ ctab,
    float*       __restrict__ out,
    int n_atoms)
{
    __shared__ float c_sh[1024];   // 4 KB
    for (int i = threadIdx.x; i < 1024; i += 256)
        c_sh[i] = ctab[i];
    __syncthreads();

    const int lane = threadIdx.x & 31;
    const int warp = threadIdx.x >> 5;
    const int s    = lane & 7;    // lane within 8-lane group
    const int g    = lane >> 3;   // atom slot within warp

    const int atom = (blockIdx.x * 8 + warp) * 4 + g;
    const bool ok  = (atom < n_atoms);
    const int a    = ok ? atom : 0;

    const float4 pa = g_packed[a];
    const int    ti = __float_as_int(pa.w);

    float G[4][8];
    #pragma unroll
    for (int t = 0; t < 4; t++)
        #pragma unroll
        for (int k = 0; k < 8; k++)
            G[t][k] = 0.0f;

    const int4*   nb4 = reinterpret_cast<const int4*>(nbr)    + (long)a * 16 + s * 2;
    const float4* ob4 = reinterpret_cast<const float4*>(offs) + (long)a * 48 + s * 6;

    #pragma unroll
    for (int half = 0; half < 2; half++) {
        const int4 nv = __ldcs(nb4 + half);

        int ia[4];
        ia[0] = (nv.x < 0) ? n_atoms : nv.x;
        ia[1] = (nv.y < 0) ? n_atoms : nv.y;
        ia[2] = (nv.z < 0) ? n_atoms : nv.z;
        ia[3] = (nv.w < 0) ? n_atoms : nv.w;

        // 4 independent LDG.128 gathers in flight
        float4 P[4];
        #pragma unroll
        for (int e = 0; e < 4; e++)
            P[e] = g_packed[ia[e]];

        const float4 f0 = __ldcs(ob4 + half * 3 + 0);
        const float4 f1 = __ldcs(ob4 + half * 3 + 1);
        const float4 f2 = __ldcs(ob4 + half * 3 + 2);
        const float ox[4] = { f0.x, f0.w, f1.z, f2.y };
        const float oy[4] = { f0.y, f1.x, f1.w, f2.z };
        const float oz[4] = { f0.z, f1.y, f2.x, f2.w };

        #pragma unroll
        for (int e = 0; e < 4; e++) {
            const float dx = P[e].x + ox[e] - pa.x;
            const float dy = P[e].y + oy[e] - pa.y;
            const float dz = P[e].z + oz[e] - pa.z;
            const int   tj = __float_as_int(P[e].w);

            const float r2 = dx * dx + dy * dy + dz * dz;
            const float r  = fsqrt_approx(r2);

            // dummy slot: tj = -1 matches no type -> contributes 0
            float h = 0.25f * fcos_approx(r * (PI_F / RC)) + 0.25f;
            h = (r < RC) ? h : 0.0f;

            const float u  = r * (1.0f / RC) - 1.0f;
            const float x  = 2.0f * u * u - 1.0f;
            const float tw = x + x;

            float T[8];
            T[1] = x;
            T[2] = tw * x - 1.0f;
            #pragma unroll
            for (int k = 3; k < 8; k++) T[k] = tw * T[k - 1] - T[k - 2];

            #pragma unroll
            for (int t = 0; t < 4; t++) {
                const float wh = (tj == t) ? h : 0.0f;
                G[t][0] += wh;                       // T0 == 1
                #pragma unroll
                for (int k = 1; k < 8; k++) G[t][k] += wh * T[k];
            }
        }
    }

    // ---- halving-butterfly reduction of 32 values over the 8-lane group ----
    float* v = &G[0][0];
    const bool hi4 = (s & 4) != 0;
    const bool hi2 = (s & 2) != 0;
    const bool hi1 = (s & 1) != 0;

    float v1[16];
    #pragma unroll
    for (int i = 0; i < 16; i++) {
        const float send = hi4 ? v[i] : v[i + 16];
        const float recv = __shfl_xor_sync(0xffffffffu, send, 4);
        v1[i] = (hi4 ? v[i + 16] : v[i]) + recv;
    }
    float v2[8];
    #pragma unroll
    for (int i = 0; i < 8; i++) {
        const float send = hi2 ? v1[i] : v1[i + 8];
        const float recv = __shfl_xor_sync(0xffffffffu, send, 2);
        v2[i] = (hi2 ? v1[i + 8] : v1[i]) + recv;
    }
    float v3[4];
    #pragma unroll
    for (int i = 0; i < 4; i++) {
        const float send = hi1 ? v2[i] : v2[i + 4];
        const float recv = __shfl_xor_sync(0xffffffffu, send, 1);
        v3[i] = (hi1 ? v2[i + 4] : v2[i]) + recv;
    }
    // lane s holds totals for t = ((s&4)>>1)|((s&2)>>1), k = (s&1)*4 + k'
    const int tl = ((s & 4) >> 1) | ((s & 2) >> 1);

    // F[t][k] = G[t][k] + G[t][0]  (folds the (T_k + 1) term; k=0 -> 2*G[t][0])
    const float g0 = __shfl_sync(0xffffffffu, v3[0], lane & ~1);
    const float F0 = v3[0] + g0;
    const float F1 = v3[1] + g0;
    const float F2 = v3[2] + g0;
    const float F3 = v3[3] + g0;

    const float4* c4p = reinterpret_cast<const float4*>(c_sh);
    const int base = ((ti * 4 + tl) * 8) * 2 + (s & 1);
    float p[8];
    #pragma unroll
    for (int d = 0; d < 8; d++) {
        const float4 c = c4p[base + d * 2];
        p[d] = c.x * F0 + c.y * F1 + c.z * F2 + c.w * F3;
    }

    float q[4];
    #pragma unroll
    for (int i = 0; i < 4; i++) {
        const float send = hi4 ? p[i] : p[i + 4];
        const float recv = __shfl_xor_sync(0xffffffffu, send, 4);
        q[i] = (hi4 ? p[i + 4] : p[i]) + recv;
    }
    float rr[2];
    #pragma unroll
    for (int i = 0; i < 2; i++) {
        const float send = hi2 ? q[i] : q[i + 2];
        const float recv = __shfl_xor_sync(0xffffffffu, send, 2);
        rr[i] = (hi2 ? q[i + 2] : q[i]) + recv;
    }
    {
        const float send = hi1 ? rr[0] : rr[1];
        const float recv = __shfl_xor_sync(0xffffffffu, send, 1);
        const float o = (hi1 ? rr[1] : rr[0]) + recv;
        if (ok) out[(long)atom * 8 + s] = o;   // 128B contiguous per warp
    }
}

extern "C" void kernel_launch(void* const* d_in, const int* in_sizes, int n_in,
                              void* d_out, int out_size) {
    const int*   types = (const int*)  d_in[0];
    const float* pos   = (const float*)d_in[1];
    const int*   nbr   = (const int*)  d_in[2];
    const float* offs  = (const float*)d_in[3];
    const float* ctab  = (const float*)d_in[4];
    float* out = (float*)d_out;

    int n_atoms = in_sizes[0];
    if (n_atoms > MAX_ATOMS) n_atoms = MAX_ATOMS;

    pack_kernel<<<(n_atoms + 1 + 255) / 256, 256>>>(types, pos, n_atoms);

    const int atoms_per_block = 32;               // 8 warps * 4 atoms
    const int grid = (n_atoms + atoms_per_block - 1) / atoms_per_block;
    radial_desc_kernel<<<grid, 256>>>(nbr, offs, ctab, out, n_atoms);
}

// round 8
// speedup vs baseline: 1.1364x; 1.1042x over previous
#include <cuda_runtime.h>

#define NN      64
#define RC      8.0f
#define PI_F    3.14159265358979323846f
#define MAX_ATOMS 32768
#define FPSCALE   32768.0f
#define INV_FPSCALE (1.0f / 32768.0f)

// fixed-point packed atoms: x:21b (+/-32), y:21b (+/-32), z:20b (+/-16), type:2b
// w.x = x[20:0] | y[10:0]<<21 ;  w.y = y[20:11] | z[19:0]<<10 | t<<30
// 8 B/atom -> 160 KB table: fits in L1 (228 KB) and stays resident.
__device__ uint2 g_q[MAX_ATOMS + 1];

static __device__ __forceinline__ float fsqrt_approx(float x) {
    float y; asm("sqrt.approx.f32 %0, %1;" : "=f"(y) : "f"(x)); return y;
}
static __device__ __forceinline__ float fcos_approx(float x) {
    float y; asm("cos.approx.f32 %0, %1;" : "=f"(y) : "f"(x)); return y;
}

__global__ void pack_kernel(const int* __restrict__ types,
                            const float* __restrict__ pos, int n)
{
    int i = blockIdx.x * blockDim.x + threadIdx.x;
    if (i < n) {
        const int xq = __float2int_rn(pos[i * 3 + 0] * FPSCALE);
        const int yq = __float2int_rn(pos[i * 3 + 1] * FPSCALE);
        const int zq = __float2int_rn(pos[i * 3 + 2] * FPSCALE);
        const unsigned t = (unsigned)types[i];
        uint2 w;
        w.x = ((unsigned)xq & 0x1FFFFFu) | ((unsigned)yq << 21);
        w.y = (((unsigned)yq >> 11) & 0x3FFu)
            | (((unsigned)zq & 0xFFFFFu) << 10)
            | (t << 30);
        g_q[i] = w;
    }
    if (i == n) {
        // dummy: x = +31 units -> r > RC for any real atom -> h = 0
        uint2 w;
        w.x = (unsigned)(31 * 32768) & 0x1FFFFFu;
        w.y = 0u;
        g_q[n] = w;
    }
}

static __device__ __forceinline__ void unpack_q(uint2 w, int& x, int& y, int& z, int& t) {
    x = ((int)(w.x << 11)) >> 11;
    const unsigned y21 = (w.x >> 21) | ((w.y & 0x3FFu) << 11);
    y = ((int)(y21 << 11)) >> 11;
    z = ((int)(w.y << 2)) >> 12;
    t = (int)(w.y >> 30);
}

// 8 lanes per atom, 4 atoms per warp, 8 warps/block -> 32 atoms/block, 625 blocks.
// __launch_bounds__(256,4): 64-reg cap -> 32 warps/SM, 1.03 waves.
// Gathers hit the L1-resident 160 KB uint2 table; nbr/offs stream via __ldcs.
__global__ __launch_bounds__(256, 4) void radial_desc_kernel(
    const int*   __restrict__ nbr,
    const float* __restrict__ offs,
    const float* __restrict__ ctab,
    float*       __restrict__ out,
    int n_atoms)
{
    __shared__ float c_sh[1024];   // 4 KB
    for (int i = threadIdx.x; i < 1024; i += 256)
        c_sh[i] = ctab[i];
    __syncthreads();

    const int lane = threadIdx.x & 31;
    const int warp = threadIdx.x >> 5;
    const int s    = lane & 7;    // lane within 8-lane group
    const int g    = lane >> 3;   // atom slot within warp

    const int atom = (blockIdx.x * 8 + warp) * 4 + g;
    const bool ok  = (atom < n_atoms);
    const int a    = ok ? atom : 0;

    int xa, ya, za, ti;
    unpack_q(__ldg(&g_q[a]), xa, ya, za, ti);

    float G[4][8];
    #pragma unroll
    for (int t = 0; t < 4; t++)
        #pragma unroll
        for (int k = 0; k < 8; k++)
            G[t][k] = 0.0f;

    const int4*   nb4 = reinterpret_cast<const int4*>(nbr)    + (long)a * 16 + s * 2;
    const float4* ob4 = reinterpret_cast<const float4*>(offs) + (long)a * 48 + s * 6;

    #pragma unroll
    for (int half = 0; half < 2; half++) {
        const int4 nv = __ldcs(nb4 + half);

        int ia[4];
        ia[0] = (nv.x < 0) ? n_atoms : nv.x;
        ia[1] = (nv.y < 0) ? n_atoms : nv.y;
        ia[2] = (nv.z < 0) ? n_atoms : nv.z;
        ia[3] = (nv.w < 0) ? n_atoms : nv.w;

        // 4 independent 8B gathers in flight, L1-resident table
        uint2 W[4];
        #pragma unroll
        for (int e = 0; e < 4; e++)
            W[e] = __ldg(&g_q[ia[e]]);

        const float4 f0 = __ldcs(ob4 + half * 3 + 0);
        const float4 f1 = __ldcs(ob4 + half * 3 + 1);
        const float4 f2 = __ldcs(ob4 + half * 3 + 2);
        const float ox[4] = { f0.x, f0.w, f1.z, f2.y };
        const float oy[4] = { f0.y, f1.x, f1.w, f2.z };
        const float oz[4] = { f0.z, f1.y, f2.x, f2.w };

        #pragma unroll
        for (int e = 0; e < 4; e++) {
            int xj, yj, zj, tj;
            unpack_q(W[e], xj, yj, zj, tj);

            // exact integer diffs; fixed-point scale folds into an FMA
            const float dx = fmaf((float)(xj - xa), INV_FPSCALE, ox[e]);
            const float dy = fmaf((float)(yj - ya), INV_FPSCALE, oy[e]);
            const float dz = fmaf((float)(zj - za), INV_FPSCALE, oz[e]);

            const float r2 = dx * dx + dy * dy + dz * dz;
            const float r  = fsqrt_approx(r2);

            // dummy slot is >RC away -> h = 0 automatically
            float h = 0.25f * fcos_approx(r * (PI_F / RC)) + 0.25f;
            h = (r < RC) ? h : 0.0f;

            const float u  = r * (1.0f / RC) - 1.0f;
            const float x  = 2.0f * u * u - 1.0f;
            const float tw = x + x;

            float T[8];
            T[1] = x;
            T[2] = tw * x - 1.0f;
            #pragma unroll
            for (int k = 3; k < 8; k++) T[k] = tw * T[k - 1] - T[k - 2];

            #pragma unroll
            for (int t = 0; t < 4; t++) {
                const float wh = (tj == t) ? h : 0.0f;
                G[t][0] += wh;                       // T0 == 1
                #pragma unroll
                for (int k = 1; k < 8; k++) G[t][k] += wh * T[k];
            }
        }
    }

    // ---- halving-butterfly reduction of 32 values over the 8-lane group ----
    float* v = &G[0][0];
    const bool hi4 = (s & 4) != 0;
    const bool hi2 = (s & 2) != 0;
    const bool hi1 = (s & 1) != 0;

    float v1[16];
    #pragma unroll
    for (int i = 0; i < 16; i++) {
        const float send = hi4 ? v[i] : v[i + 16];
        const float recv = __shfl_xor_sync(0xffffffffu, send, 4);
        v1[i] = (hi4 ? v[i + 16] : v[i]) + recv;
    }
    float v2[8];
    #pragma unroll
    for (int i = 0; i < 8; i++) {
        const float send = hi2 ? v1[i] : v1[i + 8];
        const float recv = __shfl_xor_sync(0xffffffffu, send, 2);
        v2[i] = (hi2 ? v1[i + 8] : v1[i]) + recv;
    }
    float v3[4];
    #pragma unroll
    for (int i = 0; i < 4; i++) {
        const float send = hi1 ? v2[i] : v2[i + 4];
        const float recv = __shfl_xor_sync(0xffffffffu, send, 1);
        v3[i] = (hi1 ? v2[i + 4] : v2[i]) + recv;
    }
    // lane s holds totals for t = ((s&4)>>1)|((s&2)>>1), k = (s&1)*4 + k'
    const int tl = ((s & 4) >> 1) | ((s & 2) >> 1);

    // F[t][k] = G[t][k] + G[t][0]  (folds the (T_k + 1) term; k=0 -> 2*G[t][0])
    const float g0 = __shfl_sync(0xffffffffu, v3[0], lane & ~1);
    const float F0 = v3[0] + g0;
    const float F1 = v3[1] + g0;
    const float F2 = v3[2] + g0;
    const float F3 = v3[3] + g0;

    const float4* c4p = reinterpret_cast<const float4*>(c_sh);
    const int base = ((ti * 4 + tl) * 8) * 2 + (s & 1);
    float p[8];
    #pragma unroll
    for (int d = 0; d < 8; d++) {
        const float4 c = c4p[base + d * 2];
        p[d] = c.x * F0 + c.y * F1 + c.z * F2 + c.w * F3;
    }

    float q[4];
    #pragma unroll
    for (int i = 0; i < 4; i++) {
        const float send = hi4 ? p[i] : p[i + 4];
        const float recv = __shfl_xor_sync(0xffffffffu, send, 4);
        q[i] = (hi4 ? p[i + 4] : p[i]) + recv;
    }
    float rr[2];
    #pragma unroll
    for (int i = 0; i < 2; i++) {
        const float send = hi2 ? q[i] : q[i + 2];
        const float recv = __shfl_xor_sync(0xffffffffu, send, 2);
        rr[i] = (hi2 ? q[i + 2] : q[i]) + recv;
    }
    {
        const float send = hi1 ? rr[0] : rr[1];
        const float recv = __shfl_xor_sync(0xffffffffu, send, 1);
        const float o = (hi1 ? rr[1] : rr[0]) + recv;
        if (ok) out[(long)atom * 8 + s] = o;   // 128B contiguous per warp
    }
}

extern "C" void kernel_launch(void* const* d_in, const int* in_sizes, int n_in,
                              void* d_out, int out_size) {
    const int*   types = (const int*)  d_in[0];
    const float* pos   = (const float*)d_in[1];
    const int*   nbr   = (const int*)  d_in[2];
    const float* offs  = (const float*)d_in[3];
    const float* ctab  = (const float*)d_in[4];
    float* out = (float*)d_out;

    int n_atoms = in_sizes[0];
    if (n_atoms > MAX_ATOMS) n_atoms = MAX_ATOMS;

    pack_kernel<<<(n_atoms + 1 + 255) / 256, 256>>>(types, pos, n_atoms);

    const int atoms_per_block = 32;               // 8 warps * 4 atoms
    const int grid = (n_atoms + atoms_per_block - 1) / atoms_per_block;
    radial_desc_kernel<<<grid, 256>>>(nbr, offs, ctab, out, n_atoms);
}